// round 3
// baseline (speedup 1.0000x reference)
#include <cuda_runtime.h>
#include <math.h>

#define NN 384
#define CC 128
#define HH 4
#define DD 32
#define ROWS (NN*NN)   // 147456
#define BM 128

// Scratch (device globals: allocation-free per harness rules)
__device__ float g_q[ROWS*CC];     // [b][h][n][d]
__device__ float g_k[ROWS*CC];
__device__ float g_v[ROWS*CC];
__device__ float g_gate[ROWS*CC];  // [row][c]
__device__ float g_wa[ROWS*CC];    // [b][n][c], c = h*32+d
__device__ float g_bias[HH*ROWS];  // [h][i][j]

// ---------------------------------------------------------------------------
// Kernel 1: fused LayerNorm + Q/K/V/Gate projections + per-head bias einsum
// Block: 256 threads, BM=128 rows. smem: xst[c][r] (LN'd X, transposed),
// ws[c][o] (weight chunk, transposed), wb (w_bias copy).
// ---------------------------------------------------------------------------
__global__ __launch_bounds__(256) void k_proj(
    const float* __restrict__ pair,
    const float* __restrict__ ln_w, const float* __restrict__ ln_b,
    const float* __restrict__ w_bias,
    const float* __restrict__ w_q, const float* __restrict__ w_k,
    const float* __restrict__ w_v, const float* __restrict__ w_gate)
{
    extern __shared__ float sm[];
    float* xst = sm;            // 128*128  [c][r]
    float* ws  = sm + 16384;    // 128*128  [c][o]
    float* wb  = sm + 32768;    // 512
    const int t = threadIdx.x, warp = t >> 5, lane = t & 31;
    const long row0 = (long)blockIdx.x * BM;

    for (int i = t; i < 512; i += 256) wb[i] = w_bias[i];

    // ---- Phase A: LayerNorm, store transposed ----
    const int c0 = lane * 4;
    const float4 lw = *(const float4*)(ln_w + c0);
    const float4 lb = *(const float4*)(ln_b + c0);
    for (int rr = warp * 16; rr < warp * 16 + 16; ++rr) {
        const float4 v = ((const float4*)(pair + (row0 + rr) * CC))[lane];
        float s = v.x + v.y + v.z + v.w;
        #pragma unroll
        for (int o = 16; o; o >>= 1) s += __shfl_xor_sync(0xffffffffu, s, o);
        const float mu = s * (1.0f / CC);
        const float dx = v.x - mu, dy = v.y - mu, dz = v.z - mu, dw = v.w - mu;
        float s2 = dx*dx + dy*dy + dz*dz + dw*dw;
        #pragma unroll
        for (int o = 16; o; o >>= 1) s2 += __shfl_xor_sync(0xffffffffu, s2, o);
        const float rstd = rsqrtf(s2 * (1.0f / CC) + 1e-5f);
        xst[(c0 + 0) * BM + rr] = dx * rstd * lw.x + lb.x;
        xst[(c0 + 1) * BM + rr] = dy * rstd * lw.y + lb.y;
        xst[(c0 + 2) * BM + rr] = dz * rstd * lw.z + lb.z;
        xst[(c0 + 3) * BM + rr] = dw * rstd * lw.w + lb.w;
    }
    __syncthreads();

    // ---- Phase B: 4 GEMM chunks (q, k, v, gate), 8x8 register tiles ----
    const int rg = t >> 4, cg = t & 15;
    const float* Wm[4] = {w_q, w_k, w_v, w_gate};
    for (int m = 0; m < 4; ++m) {
        if (m) __syncthreads();             // previous ws reads done
        const float* W = Wm[m];
        for (int i = t; i < 16384; i += 256) {
            const int o = i >> 7, c = i & 127;
            ws[c * CC + o] = W[i];          // transpose to [c][o]
        }
        __syncthreads();

        float acc[8][8];
        #pragma unroll
        for (int i = 0; i < 8; ++i)
            #pragma unroll
            for (int j = 0; j < 8; ++j) acc[i][j] = 0.f;

        #pragma unroll 8
        for (int k = 0; k < CC; ++k) {
            const float4 a0 = *(const float4*)&xst[k * BM + rg * 8];
            const float4 a1 = *(const float4*)&xst[k * BM + rg * 8 + 4];
            const float4 b0 = *(const float4*)&ws [k * CC + cg * 8];
            const float4 b1 = *(const float4*)&ws [k * CC + cg * 8 + 4];
            const float a[8] = {a0.x,a0.y,a0.z,a0.w,a1.x,a1.y,a1.z,a1.w};
            const float b[8] = {b0.x,b0.y,b0.z,b0.w,b1.x,b1.y,b1.z,b1.w};
            #pragma unroll
            for (int i = 0; i < 8; ++i)
                #pragma unroll
                for (int j = 0; j < 8; ++j) acc[i][j] += a[i] * b[j];
        }

        #pragma unroll
        for (int i = 0; i < 8; ++i) {
            const long R = row0 + rg * 8 + i;
            if (m < 3) {
                const int bidx = (int)(R / NN), nn = (int)(R % NN);
                float* dst = (m == 0 ? g_q : (m == 1 ? g_k : g_v));
                const int o0 = cg * 8;
                const int h = o0 >> 5, d0 = o0 & 31;
                float* p = dst + (((long)(bidx * HH + h) * NN + nn) * DD + d0);
                float4 r0 = {acc[i][0], acc[i][1], acc[i][2], acc[i][3]};
                float4 r1 = {acc[i][4], acc[i][5], acc[i][6], acc[i][7]};
                *(float4*)(p)     = r0;
                *(float4*)(p + 4) = r1;
            } else {
                float* p = g_gate + R * CC + cg * 8;
                float4 r0, r1;
                r0.x = 1.f / (1.f + __expf(-acc[i][0]));
                r0.y = 1.f / (1.f + __expf(-acc[i][1]));
                r0.z = 1.f / (1.f + __expf(-acc[i][2]));
                r0.w = 1.f / (1.f + __expf(-acc[i][3]));
                r1.x = 1.f / (1.f + __expf(-acc[i][4]));
                r1.y = 1.f / (1.f + __expf(-acc[i][5]));
                r1.z = 1.f / (1.f + __expf(-acc[i][6]));
                r1.w = 1.f / (1.f + __expf(-acc[i][7]));
                *(float4*)(p)     = r0;
                *(float4*)(p + 4) = r1;
            }
        }
    }
    __syncthreads();

    // ---- Phase C: nonbatched pair bias: bias[h][R] = xst[:,R] . w_bias[h] ----
    for (int task = t; task < 512; task += 256) {
        const int rr = task & 127;
        const int h  = task >> 7;
        float s = 0.f;
        #pragma unroll 8
        for (int k = 0; k < CC; ++k) s += xst[k * BM + rr] * wb[h * CC + k];
        g_bias[(long)h * ROWS + row0 + rr] = s;
    }
}

// ---------------------------------------------------------------------------
// Kernel 2: attention per (b,h). 1536 blocks, 256 threads.
// K/V staged in smem with stride 33 (conflict-free lane-owns-key access).
// Each warp processes 4 query rows at a time (amortizes K smem reads).
// ---------------------------------------------------------------------------
__global__ __launch_bounds__(256) void k_attn(const int* __restrict__ mask)
{
    extern __shared__ float sm[];
    float* ks = sm;                        // 384*33
    float* vs = sm + NN * 33;              // 384*33
    float* pr = sm + 2 * NN * 33;          // 8 warps * 4 rows * 384
    int*   mk = (int*)(sm + 2 * NN * 33 + 8 * 4 * NN);  // 384
    const int t = threadIdx.x, warp = t >> 5, lane = t & 31;
    const int b = blockIdx.x >> 2, h = blockIdx.x & 3;

    const float* __restrict__ kg = g_k + (long)(b * HH + h) * NN * DD;
    const float* __restrict__ vg = g_v + (long)(b * HH + h) * NN * DD;
    for (int i = t; i < NN * DD; i += 256) {
        const int j = i >> 5, d = i & 31;
        ks[j * 33 + d] = kg[i];
        vs[j * 33 + d] = vg[i];
    }
    for (int j = t; j < NN; j += 256) mk[j] = __ldg(mask + b * NN + j);
    __syncthreads();

    const float* __restrict__ qg = g_q + (long)(b * HH + h) * NN * DD;
    const float* __restrict__ bias_h = g_bias + (long)h * ROWS;
    float* prw = pr + warp * 4 * NN;

    for (int g = 0; g < 12; ++g) {
        const int i0 = g * 32 + warp * 4;
        float qd[4];
        #pragma unroll
        for (int r = 0; r < 4; ++r) qd[r] = qg[(i0 + r) * DD + lane];

        float lg[4][12];
        #pragma unroll
        for (int r = 0; r < 4; ++r)
            #pragma unroll
            for (int m = 0; m < 12; ++m) lg[r][m] = 0.f;

        #pragma unroll
        for (int d = 0; d < DD; ++d) {
            const float qv0 = __shfl_sync(0xffffffffu, qd[0], d);
            const float qv1 = __shfl_sync(0xffffffffu, qd[1], d);
            const float qv2 = __shfl_sync(0xffffffffu, qd[2], d);
            const float qv3 = __shfl_sync(0xffffffffu, qd[3], d);
            #pragma unroll
            for (int m = 0; m < 12; ++m) {
                const float kv = ks[(lane + 32 * m) * 33 + d];
                lg[0][m] += qv0 * kv;
                lg[1][m] += qv1 * kv;
                lg[2][m] += qv2 * kv;
                lg[3][m] += qv3 * kv;
            }
        }

        // softmax per row (scale, +bias, mask, max, exp, sum)
        #pragma unroll
        for (int r = 0; r < 4; ++r) {
            const int i = i0 + r;
            const float* __restrict__ bp = bias_h + (long)i * NN;
            float mx = -3e38f;
            #pragma unroll
            for (int m = 0; m < 12; ++m) {
                const int j = lane + 32 * m;
                float x = lg[r][m] * 0.17677669529663687f + bp[j];
                if (mk[j] == 0) x = -1e9f;
                lg[r][m] = x;
                mx = fmaxf(mx, x);
            }
            #pragma unroll
            for (int o = 16; o; o >>= 1) mx = fmaxf(mx, __shfl_xor_sync(0xffffffffu, mx, o));
            float s = 0.f;
            #pragma unroll
            for (int m = 0; m < 12; ++m) {
                const float e = __expf(lg[r][m] - mx);
                lg[r][m] = e;
                s += e;
            }
            #pragma unroll
            for (int o = 16; o; o >>= 1) s += __shfl_xor_sync(0xffffffffu, s, o);
            const float inv = 1.0f / s;
            #pragma unroll
            for (int m = 0; m < 12; ++m) prw[r * NN + lane + 32 * m] = lg[r][m] * inv;
        }
        __syncwarp();

        // PV: out[d=lane] = sum_j p[j] * v[j][lane]
        float out0 = 0.f, out1 = 0.f, out2 = 0.f, out3 = 0.f;
        #pragma unroll 4
        for (int j = 0; j < NN; j += 4) {
            const float v0 = vs[(j + 0) * 33 + lane];
            const float v1 = vs[(j + 1) * 33 + lane];
            const float v2 = vs[(j + 2) * 33 + lane];
            const float v3 = vs[(j + 3) * 33 + lane];
            const float4 p0 = *(const float4*)&prw[0 * NN + j];
            const float4 p1 = *(const float4*)&prw[1 * NN + j];
            const float4 p2 = *(const float4*)&prw[2 * NN + j];
            const float4 p3 = *(const float4*)&prw[3 * NN + j];
            out0 += p0.x * v0 + p0.y * v1 + p0.z * v2 + p0.w * v3;
            out1 += p1.x * v0 + p1.y * v1 + p1.z * v2 + p1.w * v3;
            out2 += p2.x * v0 + p2.y * v1 + p2.z * v2 + p2.w * v3;
            out3 += p3.x * v0 + p3.y * v1 + p3.z * v2 + p3.w * v3;
        }
        g_wa[((long)b * NN + (i0 + 0)) * CC + h * DD + lane] = out0;
        g_wa[((long)b * NN + (i0 + 1)) * CC + h * DD + lane] = out1;
        g_wa[((long)b * NN + (i0 + 2)) * CC + h * DD + lane] = out2;
        g_wa[((long)b * NN + (i0 + 3)) * CC + h * DD + lane] = out3;
        __syncwarp();   // prw reads done before next iteration overwrites
    }
}

// ---------------------------------------------------------------------------
// Kernel 3: out = (wa * gate) @ w_out^T. Same GEMM scheme as kernel 1.
// ---------------------------------------------------------------------------
__global__ __launch_bounds__(256) void k_out(const float* __restrict__ w_out,
                                             float* __restrict__ out)
{
    extern __shared__ float sm[];
    float* as = sm;           // [c][r]
    float* ws = sm + 16384;   // [c][o]
    const int t = threadIdx.x;
    const long row0 = (long)blockIdx.x * BM;

    for (int i = t; i < 16384; i += 256) {
        const int o = i >> 7, c = i & 127;
        ws[c * CC + o] = w_out[i];
    }
    for (int i = t; i < 4096; i += 256) {
        const int idx = i * 4;
        const int r = idx >> 7, c = idx & 127;
        const float4 wv = *(const float4*)&g_wa  [(row0 + r) * CC + c];
        const float4 gv = *(const float4*)&g_gate[(row0 + r) * CC + c];
        as[(c + 0) * BM + r] = wv.x * gv.x;
        as[(c + 1) * BM + r] = wv.y * gv.y;
        as[(c + 2) * BM + r] = wv.z * gv.z;
        as[(c + 3) * BM + r] = wv.w * gv.w;
    }
    __syncthreads();

    const int rg = t >> 4, cg = t & 15;
    float acc[8][8];
    #pragma unroll
    for (int i = 0; i < 8; ++i)
        #pragma unroll
        for (int j = 0; j < 8; ++j) acc[i][j] = 0.f;

    #pragma unroll 8
    for (int k = 0; k < CC; ++k) {
        const float4 a0 = *(const float4*)&as[k * BM + rg * 8];
        const float4 a1 = *(const float4*)&as[k * BM + rg * 8 + 4];
        const float4 b0 = *(const float4*)&ws[k * CC + cg * 8];
        const float4 b1 = *(const float4*)&ws[k * CC + cg * 8 + 4];
        const float a[8] = {a0.x,a0.y,a0.z,a0.w,a1.x,a1.y,a1.z,a1.w};
        const float b[8] = {b0.x,b0.y,b0.z,b0.w,b1.x,b1.y,b1.z,b1.w};
        #pragma unroll
        for (int i = 0; i < 8; ++i)
            #pragma unroll
            for (int j = 0; j < 8; ++j) acc[i][j] += a[i] * b[j];
    }

    #pragma unroll
    for (int i = 0; i < 8; ++i) {
        float* p = out + (row0 + rg * 8 + i) * CC + cg * 8;
        float4 r0 = {acc[i][0], acc[i][1], acc[i][2], acc[i][3]};
        float4 r1 = {acc[i][4], acc[i][5], acc[i][6], acc[i][7]};
        *(float4*)(p)     = r0;
        *(float4*)(p + 4) = r1;
    }
}

// ---------------------------------------------------------------------------
extern "C" void kernel_launch(void* const* d_in, const int* in_sizes, int n_in,
                              void* d_out, int out_size)
{
    const float* pair   = (const float*)d_in[0];
    const int*   mask   = (const int*)  d_in[1];
    const float* ln_w   = (const float*)d_in[2];
    const float* ln_b   = (const float*)d_in[3];
    const float* w_bias = (const float*)d_in[4];
    const float* w_q    = (const float*)d_in[5];
    const float* w_k    = (const float*)d_in[6];
    const float* w_v    = (const float*)d_in[7];
    const float* w_gate = (const float*)d_in[8];
    const float* w_out  = (const float*)d_in[9];
    float* out = (float*)d_out;

    const int smem1 = (16384 + 16384 + 512) * 4;                 // 133,120 B
    const int smem2 = (2 * NN * 33 + 8 * 4 * NN) * 4 + NN * 4;   // 152,064 B
    const int smem3 = 32768 * 4;                                 // 131,072 B
    cudaFuncSetAttribute(k_proj, cudaFuncAttributeMaxDynamicSharedMemorySize, smem1);
    cudaFuncSetAttribute(k_attn, cudaFuncAttributeMaxDynamicSharedMemorySize, smem2);
    cudaFuncSetAttribute(k_out,  cudaFuncAttributeMaxDynamicSharedMemorySize, smem3);

    k_proj<<<ROWS / BM, 256, smem1>>>(pair, ln_w, ln_b, w_bias, w_q, w_k, w_v, w_gate);
    k_attn<<<NN * HH, 256, smem2>>>(mask);
    k_out <<<ROWS / BM, 256, smem3>>>(w_out, out);
}

// round 4
// speedup vs baseline: 1.6178x; 1.6178x over previous
#include <cuda_runtime.h>
#include <cstdint>
#include <math.h>

#define NN 384
#define CC 128
#define HH 4
#define DD 32
#define ROWS (NN*NN)   // 147456
#define BM 128
#define XS 132         // padded k-stride for 128-wide tf32 smem tiles

// Scratch (device globals: allocation-free per harness rules)
__device__ float g_q[ROWS*CC];     // [b][h][n][d]
__device__ float g_k[ROWS*CC];
__device__ float g_v[ROWS*CC];
__device__ float g_gate[ROWS*CC];  // [row][c]
__device__ float g_wa[ROWS*CC];    // [b][n][c], c = h*32+d
__device__ float g_bias[HH*ROWS];  // [h][i][j]

__device__ __forceinline__ uint32_t f2tf(float x) {
    uint32_t u;
    asm("cvt.rna.tf32.f32 %0, %1;" : "=r"(u) : "f"(x));
    return u;
}

__device__ __forceinline__ void mma8(float* d, const uint32_t* a, const uint32_t* b) {
    asm("mma.sync.aligned.m16n8k8.row.col.f32.tf32.tf32.f32 "
        "{%0,%1,%2,%3},{%4,%5,%6,%7},{%8,%9},{%0,%1,%2,%3};"
        : "+f"(d[0]), "+f"(d[1]), "+f"(d[2]), "+f"(d[3])
        : "r"(a[0]), "r"(a[1]), "r"(a[2]), "r"(a[3]), "r"(b[0]), "r"(b[1]));
}

// ---------------------------------------------------------------------------
// Kernel 1: LN + Q/K/V/Gate projections (tf32 mma) + per-head pair bias
// Block 256 thr (8 warps as 4m x 2n grid of 32x64 warp tiles over 128x128).
// ---------------------------------------------------------------------------
__global__ __launch_bounds__(256) void k_proj(
    const float* __restrict__ pair,
    const float* __restrict__ ln_w, const float* __restrict__ ln_b,
    const float* __restrict__ w_bias,
    const float* __restrict__ w_q, const float* __restrict__ w_k,
    const float* __restrict__ w_v, const float* __restrict__ w_gate)
{
    extern __shared__ uint32_t sm[];
    uint32_t* xs = sm;                 // [128][XS] tf32 LN(x), row-major [r][c]
    uint32_t* ws = sm + 128 * XS;      // [128][XS] tf32 W,    row-major [o][c]
    float*    wb = (float*)(sm + 2 * 128 * XS);  // 512
    const int t = threadIdx.x, warp = t >> 5, lane = t & 31;
    const int gid = lane >> 2, tig = lane & 3;
    const int wm = warp >> 1, wn = warp & 1;
    const long row0 = (long)blockIdx.x * BM;

    for (int i = t; i < 512; i += 256) wb[i] = w_bias[i];

    // ---- LayerNorm, store tf32 row-major ----
    {
        const int c0 = lane * 4;
        const float4 lw = *(const float4*)(ln_w + c0);
        const float4 lb = *(const float4*)(ln_b + c0);
        for (int rr = warp * 16; rr < warp * 16 + 16; ++rr) {
            const float4 v = ((const float4*)(pair + (row0 + rr) * CC))[lane];
            float s = v.x + v.y + v.z + v.w;
            #pragma unroll
            for (int o = 16; o; o >>= 1) s += __shfl_xor_sync(0xffffffffu, s, o);
            const float mu = s * (1.0f / CC);
            const float dx = v.x - mu, dy = v.y - mu, dz = v.z - mu, dw = v.w - mu;
            float s2 = dx*dx + dy*dy + dz*dz + dw*dw;
            #pragma unroll
            for (int o = 16; o; o >>= 1) s2 += __shfl_xor_sync(0xffffffffu, s2, o);
            const float rstd = rsqrtf(s2 * (1.0f / CC) + 1e-5f);
            xs[rr * XS + c0 + 0] = f2tf(dx * rstd * lw.x + lb.x);
            xs[rr * XS + c0 + 1] = f2tf(dy * rstd * lw.y + lb.y);
            xs[rr * XS + c0 + 2] = f2tf(dz * rstd * lw.z + lb.z);
            xs[rr * XS + c0 + 3] = f2tf(dw * rstd * lw.w + lb.w);
        }
    }
    __syncthreads();

    const float* Wm[4] = {w_q, w_k, w_v, w_gate};
    for (int m = 0; m < 4; ++m) {
        if (m) __syncthreads();
        const float* W = Wm[m];
        for (int i = t; i < 16384; i += 256)
            ws[(i >> 7) * XS + (i & 127)] = f2tf(W[i]);   // [o][c]
        __syncthreads();

        float acc[2][8][4];
        #pragma unroll
        for (int mt = 0; mt < 2; ++mt)
            #pragma unroll
            for (int nt = 0; nt < 8; ++nt)
                #pragma unroll
                for (int j = 0; j < 4; ++j) acc[mt][nt][j] = 0.f;

        #pragma unroll 4
        for (int ks = 0; ks < 16; ++ks) {
            const int k0 = ks * 8;
            uint32_t af[2][4];
            #pragma unroll
            for (int mt = 0; mt < 2; ++mt) {
                const int r = wm * 32 + mt * 16 + gid;
                af[mt][0] = xs[r * XS + k0 + tig];
                af[mt][1] = xs[(r + 8) * XS + k0 + tig];
                af[mt][2] = xs[r * XS + k0 + tig + 4];
                af[mt][3] = xs[(r + 8) * XS + k0 + tig + 4];
            }
            uint32_t bf[8][2];
            #pragma unroll
            for (int nt = 0; nt < 8; ++nt) {
                const int n0 = wn * 64 + nt * 8 + gid;
                bf[nt][0] = ws[n0 * XS + k0 + tig];
                bf[nt][1] = ws[n0 * XS + k0 + tig + 4];
            }
            #pragma unroll
            for (int mt = 0; mt < 2; ++mt)
                #pragma unroll
                for (int nt = 0; nt < 8; ++nt)
                    mma8(acc[mt][nt], af[mt], bf[nt]);
        }

        // epilogue
        #pragma unroll
        for (int mt = 0; mt < 2; ++mt) {
            #pragma unroll
            for (int nt = 0; nt < 8; ++nt) {
                const int col = wn * 64 + nt * 8 + 2 * tig;
                #pragma unroll
                for (int rg = 0; rg < 2; ++rg) {
                    const long R = row0 + wm * 32 + mt * 16 + gid + rg * 8;
                    const float v0 = acc[mt][nt][rg * 2 + 0];
                    const float v1 = acc[mt][nt][rg * 2 + 1];
                    if (m < 3) {
                        const int bidx = (int)(R / NN), nn = (int)(R % NN);
                        float* dst = (m == 0 ? g_q : (m == 1 ? g_k : g_v));
                        const int h = col >> 5, d0 = col & 31;
                        float2 r2 = {v0, v1};
                        *(float2*)(dst + (((long)(bidx * HH + h) * NN + nn) * DD + d0)) = r2;
                    } else {
                        float2 r2 = {1.f / (1.f + __expf(-v0)), 1.f / (1.f + __expf(-v1))};
                        *(float2*)(g_gate + R * CC + col) = r2;
                    }
                }
            }
        }
    }
    __syncthreads();

    // ---- pair bias: bias[h][R] = x_ln[R,:] . w_bias[h,:] (tf32-rounded x ok)
    for (int task = t; task < 512; task += 256) {
        const int rr = task & 127;
        const int h  = task >> 7;
        float s = 0.f;
        #pragma unroll 8
        for (int k = 0; k < CC; ++k)
            s += __uint_as_float(xs[rr * XS + k]) * wb[h * CC + k];
        g_bias[(long)h * ROWS + row0 + rr] = s;
    }
}

// ---------------------------------------------------------------------------
// Kernel 2: attention per (b,h), tf32 mma for QK^T and PV.
// 12 chunks of 32 query rows. QK: 8 warps split n (48 cols each).
// PV: same warps split k (their own 48 keys) — P passed via register shuffles.
// ---------------------------------------------------------------------------
#define KS_S 36
#define VS_S 40
#define OS_S 33
__global__ __launch_bounds__(256) void k_attn(const int* __restrict__ mask)
{
    extern __shared__ uint32_t sm[];
    uint32_t* Ks = sm;                       // [384][KS_S]
    uint32_t* Vs = Ks + NN * KS_S;           // [384][VS_S]
    uint32_t* Qs = Vs + NN * VS_S;           // [32][KS_S]
    float*    Os = (float*)(Qs + 32 * KS_S); // [8][32][OS_S]
    float*  redm = Os + 8 * 32 * OS_S;       // [8][32]
    float*  reds = redm + 8 * 32;            // [8][32]
    int*      mk = (int*)(reds + 8 * 32);    // [384]

    const int t = threadIdx.x, warp = t >> 5, lane = t & 31;
    const int gid = lane >> 2, tig = lane & 3;
    const int b = blockIdx.x >> 2, h = blockIdx.x & 3;

    const float* __restrict__ qg = g_q + (long)(b * HH + h) * NN * DD;
    const float* __restrict__ kg = g_k + (long)(b * HH + h) * NN * DD;
    const float* __restrict__ vg = g_v + (long)(b * HH + h) * NN * DD;
    const float* __restrict__ bias_h = g_bias + (long)h * ROWS;

    for (int i = t * 4; i < NN * DD; i += 1024) {
        const int j = i >> 5, d = i & 31;
        const float4 kv = *(const float4*)(kg + i);
        const float4 vv = *(const float4*)(vg + i);
        Ks[j * KS_S + d + 0] = f2tf(kv.x); Ks[j * KS_S + d + 1] = f2tf(kv.y);
        Ks[j * KS_S + d + 2] = f2tf(kv.z); Ks[j * KS_S + d + 3] = f2tf(kv.w);
        Vs[j * VS_S + d + 0] = f2tf(vv.x); Vs[j * VS_S + d + 1] = f2tf(vv.y);
        Vs[j * VS_S + d + 2] = f2tf(vv.z); Vs[j * VS_S + d + 3] = f2tf(vv.w);
    }
    for (int j = t; j < NN; j += 256) mk[j] = __ldg(mask + b * NN + j);

    for (int chunk = 0; chunk < 12; ++chunk) {
        const int row0 = chunk * 32;
        __syncthreads();   // Os/Qs reuse from previous chunk complete
        for (int i = t * 4; i < 32 * DD; i += 1024) {
            const int r = i >> 5, d = i & 31;
            const float4 v = *(const float4*)(qg + (long)(row0 + r) * DD + d);
            Qs[r * KS_S + d + 0] = f2tf(v.x); Qs[r * KS_S + d + 1] = f2tf(v.y);
            Qs[r * KS_S + d + 2] = f2tf(v.z); Qs[r * KS_S + d + 3] = f2tf(v.w);
        }
        __syncthreads();

        // ---- QK^T: warp covers 32 rows x 48 cols (2 m-tiles x 6 n-tiles) ----
        float sc[2][6][4];
        #pragma unroll
        for (int mt = 0; mt < 2; ++mt)
            #pragma unroll
            for (int nt = 0; nt < 6; ++nt)
                #pragma unroll
                for (int j = 0; j < 4; ++j) sc[mt][nt][j] = 0.f;

        #pragma unroll
        for (int ks = 0; ks < 4; ++ks) {
            const int k0 = ks * 8;
            uint32_t af[2][4];
            #pragma unroll
            for (int mt = 0; mt < 2; ++mt) {
                const int r = mt * 16 + gid;
                af[mt][0] = Qs[r * KS_S + k0 + tig];
                af[mt][1] = Qs[(r + 8) * KS_S + k0 + tig];
                af[mt][2] = Qs[r * KS_S + k0 + tig + 4];
                af[mt][3] = Qs[(r + 8) * KS_S + k0 + tig + 4];
            }
            uint32_t bf[6][2];
            #pragma unroll
            for (int nt = 0; nt < 6; ++nt) {
                const int n0 = warp * 48 + nt * 8 + gid;
                bf[nt][0] = Ks[n0 * KS_S + k0 + tig];
                bf[nt][1] = Ks[n0 * KS_S + k0 + tig + 4];
            }
            #pragma unroll
            for (int mt = 0; mt < 2; ++mt)
                #pragma unroll
                for (int nt = 0; nt < 6; ++nt)
                    mma8(sc[mt][nt], af[mt], bf[nt]);
        }

        // ---- scale + bias + mask; per-row max ----
        float rmax[2][2] = {{-3e38f, -3e38f}, {-3e38f, -3e38f}};
        #pragma unroll
        for (int mt = 0; mt < 2; ++mt)
            #pragma unroll
            for (int nt = 0; nt < 6; ++nt)
                #pragma unroll
                for (int rg = 0; rg < 2; ++rg)
                    #pragma unroll
                    for (int cj = 0; cj < 2; ++cj) {
                        const int i = row0 + mt * 16 + rg * 8 + gid;
                        const int j = warp * 48 + nt * 8 + 2 * tig + cj;
                        float x = sc[mt][nt][rg * 2 + cj] * 0.17677669529663687f
                                  + bias_h[(long)i * NN + j];
                        if (mk[j] == 0) x = -1e9f;
                        sc[mt][nt][rg * 2 + cj] = x;
                        rmax[mt][rg] = fmaxf(rmax[mt][rg], x);
                    }
        #pragma unroll
        for (int mt = 0; mt < 2; ++mt)
            #pragma unroll
            for (int rg = 0; rg < 2; ++rg) {
                float v = rmax[mt][rg];
                v = fmaxf(v, __shfl_xor_sync(0xffffffffu, v, 1));
                v = fmaxf(v, __shfl_xor_sync(0xffffffffu, v, 2));
                rmax[mt][rg] = v;
                if (tig == 0) redm[warp * 32 + mt * 16 + rg * 8 + gid] = v;
            }
        __syncthreads();
        float gmax[2][2];
        #pragma unroll
        for (int mt = 0; mt < 2; ++mt)
            #pragma unroll
            for (int rg = 0; rg < 2; ++rg) {
                const int r = mt * 16 + rg * 8 + gid;
                float v = redm[r];
                #pragma unroll
                for (int w = 1; w < 8; ++w) v = fmaxf(v, redm[w * 32 + r]);
                gmax[mt][rg] = v;
            }
        // exp + row sums
        float rsum[2][2] = {{0.f, 0.f}, {0.f, 0.f}};
        #pragma unroll
        for (int mt = 0; mt < 2; ++mt)
            #pragma unroll
            for (int nt = 0; nt < 6; ++nt)
                #pragma unroll
                for (int rg = 0; rg < 2; ++rg)
                    #pragma unroll
                    for (int cj = 0; cj < 2; ++cj) {
                        const float e = __expf(sc[mt][nt][rg * 2 + cj] - gmax[mt][rg]);
                        sc[mt][nt][rg * 2 + cj] = e;
                        rsum[mt][rg] += e;
                    }
        #pragma unroll
        for (int mt = 0; mt < 2; ++mt)
            #pragma unroll
            for (int rg = 0; rg < 2; ++rg) {
                float v = rsum[mt][rg];
                v += __shfl_xor_sync(0xffffffffu, v, 1);
                v += __shfl_xor_sync(0xffffffffu, v, 2);
                if (tig == 0) reds[warp * 32 + mt * 16 + rg * 8 + gid] = v;
            }
        __syncthreads();
        float ginv[2][2];
        #pragma unroll
        for (int mt = 0; mt < 2; ++mt)
            #pragma unroll
            for (int rg = 0; rg < 2; ++rg) {
                const int r = mt * 16 + rg * 8 + gid;
                float v = 0.f;
                #pragma unroll
                for (int w = 0; w < 8; ++w) v += reds[w * 32 + r];
                ginv[mt][rg] = 1.0f / v;
            }
        // normalize probs in-register
        #pragma unroll
        for (int mt = 0; mt < 2; ++mt)
            #pragma unroll
            for (int nt = 0; nt < 6; ++nt)
                #pragma unroll
                for (int rg = 0; rg < 2; ++rg) {
                    sc[mt][nt][rg * 2 + 0] *= ginv[mt][rg];
                    sc[mt][nt][rg * 2 + 1] *= ginv[mt][rg];
                }

        // ---- PV: warp's own 48 keys; A-frags from sc via shuffles ----
        float oac[2][4][4];
        #pragma unroll
        for (int mt = 0; mt < 2; ++mt)
            #pragma unroll
            for (int nv = 0; nv < 4; ++nv)
                #pragma unroll
                for (int j = 0; j < 4; ++j) oac[mt][nv][j] = 0.f;

        const int base = lane & ~3;
        const int s0 = base + (tig >> 1);
        const int s1 = base + (tig >> 1) + 2;
        const bool odd = (tig & 1);
        #pragma unroll
        for (int kb = 0; kb < 6; ++kb) {
            uint32_t af[2][4];
            #pragma unroll
            for (int mt = 0; mt < 2; ++mt) {
                const uint32_t u0 = f2tf(sc[mt][kb][0]);
                const uint32_t u1 = f2tf(sc[mt][kb][1]);
                const uint32_t u2 = f2tf(sc[mt][kb][2]);
                const uint32_t u3 = f2tf(sc[mt][kb][3]);
                const uint32_t v00 = __shfl_sync(0xffffffffu, u0, s0);
                const uint32_t v01 = __shfl_sync(0xffffffffu, u1, s0);
                const uint32_t v20 = __shfl_sync(0xffffffffu, u2, s0);
                const uint32_t v21 = __shfl_sync(0xffffffffu, u3, s0);
                const uint32_t w00 = __shfl_sync(0xffffffffu, u0, s1);
                const uint32_t w01 = __shfl_sync(0xffffffffu, u1, s1);
                const uint32_t w20 = __shfl_sync(0xffffffffu, u2, s1);
                const uint32_t w21 = __shfl_sync(0xffffffffu, u3, s1);
                af[mt][0] = odd ? v01 : v00;
                af[mt][1] = odd ? v21 : v20;
                af[mt][2] = odd ? w01 : w00;
                af[mt][3] = odd ? w21 : w20;
            }
            const int k0 = warp * 48 + kb * 8;
            uint32_t bf[4][2];
            #pragma unroll
            for (int nv = 0; nv < 4; ++nv) {
                bf[nv][0] = Vs[(k0 + tig) * VS_S + nv * 8 + gid];
                bf[nv][1] = Vs[(k0 + tig + 4) * VS_S + nv * 8 + gid];
            }
            #pragma unroll
            for (int mt = 0; mt < 2; ++mt)
                #pragma unroll
                for (int nv = 0; nv < 4; ++nv)
                    mma8(oac[mt][nv], af[mt], bf[nv]);
        }

        // partial O to smem, then block reduce over 8 warps
        #pragma unroll
        for (int mt = 0; mt < 2; ++mt)
            #pragma unroll
            for (int nv = 0; nv < 4; ++nv)
                #pragma unroll
                for (int rg = 0; rg < 2; ++rg) {
                    const int r = mt * 16 + rg * 8 + gid;
                    Os[(warp * 32 + r) * OS_S + nv * 8 + 2 * tig + 0] = oac[mt][nv][rg * 2 + 0];
                    Os[(warp * 32 + r) * OS_S + nv * 8 + 2 * tig + 1] = oac[mt][nv][rg * 2 + 1];
                }
        __syncthreads();
        for (int e = t; e < 32 * 32; e += 256) {
            const int r = e >> 5, d = e & 31;
            float s = 0.f;
            #pragma unroll
            for (int w = 0; w < 8; ++w) s += Os[(w * 32 + r) * OS_S + d];
            g_wa[((long)b * NN + row0 + r) * CC + h * DD + d] = s;
        }
    }
}

// ---------------------------------------------------------------------------
// Kernel 3: out = (wa * gate) @ w_out^T, tf32 mma, same scheme as k_proj.
// ---------------------------------------------------------------------------
__global__ __launch_bounds__(256) void k_out(const float* __restrict__ w_out,
                                             float* __restrict__ out)
{
    extern __shared__ uint32_t sm[];
    uint32_t* as = sm;             // [128][XS]
    uint32_t* ws = sm + 128 * XS;  // [128][XS]
    const int t = threadIdx.x, warp = t >> 5, lane = t & 31;
    const int gid = lane >> 2, tig = lane & 3;
    const int wm = warp >> 1, wn = warp & 1;
    const long row0 = (long)blockIdx.x * BM;

    for (int i = t; i < 16384; i += 256)
        ws[(i >> 7) * XS + (i & 127)] = f2tf(w_out[i]);
    for (int i = t * 4; i < 16384; i += 1024) {
        const int r = i >> 7, c = i & 127;
        const float4 wv = *(const float4*)&g_wa  [(row0 + r) * CC + c];
        const float4 gv = *(const float4*)&g_gate[(row0 + r) * CC + c];
        as[r * XS + c + 0] = f2tf(wv.x * gv.x);
        as[r * XS + c + 1] = f2tf(wv.y * gv.y);
        as[r * XS + c + 2] = f2tf(wv.z * gv.z);
        as[r * XS + c + 3] = f2tf(wv.w * gv.w);
    }
    __syncthreads();

    float acc[2][8][4];
    #pragma unroll
    for (int mt = 0; mt < 2; ++mt)
        #pragma unroll
        for (int nt = 0; nt < 8; ++nt)
            #pragma unroll
            for (int j = 0; j < 4; ++j) acc[mt][nt][j] = 0.f;

    #pragma unroll 4
    for (int ks = 0; ks < 16; ++ks) {
        const int k0 = ks * 8;
        uint32_t af[2][4];
        #pragma unroll
        for (int mt = 0; mt < 2; ++mt) {
            const int r = wm * 32 + mt * 16 + gid;
            af[mt][0] = as[r * XS + k0 + tig];
            af[mt][1] = as[(r + 8) * XS + k0 + tig];
            af[mt][2] = as[r * XS + k0 + tig + 4];
            af[mt][3] = as[(r + 8) * XS + k0 + tig + 4];
        }
        uint32_t bf[8][2];
        #pragma unroll
        for (int nt = 0; nt < 8; ++nt) {
            const int n0 = wn * 64 + nt * 8 + gid;
            bf[nt][0] = ws[n0 * XS + k0 + tig];
            bf[nt][1] = ws[n0 * XS + k0 + tig + 4];
        }
        #pragma unroll
        for (int mt = 0; mt < 2; ++mt)
            #pragma unroll
            for (int nt = 0; nt < 8; ++nt)
                mma8(acc[mt][nt], af[mt], bf[nt]);
    }

    #pragma unroll
    for (int mt = 0; mt < 2; ++mt)
        #pragma unroll
        for (int nt = 0; nt < 8; ++nt) {
            const int col = wn * 64 + nt * 8 + 2 * tig;
            #pragma unroll
            for (int rg = 0; rg < 2; ++rg) {
                const long R = row0 + wm * 32 + mt * 16 + gid + rg * 8;
                float2 r2 = {acc[mt][nt][rg * 2 + 0], acc[mt][nt][rg * 2 + 1]};
                *(float2*)(out + R * CC + col) = r2;
            }
        }
}

// ---------------------------------------------------------------------------
extern "C" void kernel_launch(void* const* d_in, const int* in_sizes, int n_in,
                              void* d_out, int out_size)
{
    const float* pair   = (const float*)d_in[0];
    const int*   mask   = (const int*)  d_in[1];
    const float* ln_w   = (const float*)d_in[2];
    const float* ln_b   = (const float*)d_in[3];
    const float* w_bias = (const float*)d_in[4];
    const float* w_q    = (const float*)d_in[5];
    const float* w_k    = (const float*)d_in[6];
    const float* w_v    = (const float*)d_in[7];
    const float* w_gate = (const float*)d_in[8];
    const float* w_out  = (const float*)d_in[9];
    float* out = (float*)d_out;

    const int smem1 = (2 * 128 * XS + 512) * 4;                          // 137,216 B
    const int smem2 = (NN * KS_S + NN * VS_S + 32 * KS_S
                       + 8 * 32 * OS_S + 2 * 8 * 32 + NN) * 4;           // 158,720 B
    const int smem3 = 2 * 128 * XS * 4;                                  // 135,168 B
    cudaFuncSetAttribute(k_proj, cudaFuncAttributeMaxDynamicSharedMemorySize, smem1);
    cudaFuncSetAttribute(k_attn, cudaFuncAttributeMaxDynamicSharedMemorySize, smem2);
    cudaFuncSetAttribute(k_out,  cudaFuncAttributeMaxDynamicSharedMemorySize, smem3);

    k_proj<<<ROWS / BM, 256, smem1>>>(pair, ln_w, ln_b, w_bias, w_q, w_k, w_v, w_gate);
    k_attn<<<NN * HH, 256, smem2>>>(mask);
    k_out <<<ROWS / BM, 256, smem3>>>(w_out, out);
}